// round 3
// baseline (speedup 1.0000x reference)
#include <cuda_runtime.h>
#include <math.h>

#define B_ 32
#define S_ 8400
#define H_ 256
#define C_ 80
#define K_ 300
#define ROWS_TOTAL (B_*S_)
#define SB 260
#define MAXC 512

// Output layout (flattened reference tuple, row-major, fp32):
#define OFF_TARGET 0
#define OFF_REFP   2457600
#define OFF_BOXES  2496000
#define OFF_LOGITS 2534400
#define OFF_MASKED 3302400

__device__ float g_encoded[(size_t)ROWS_TOTAL * H_];   // 275 MB scratch
__device__ float g_rowmax[ROWS_TOTAL];
__device__ int   g_topk[B_ * K_];
__device__ float g_thr[B_];
__device__ int   g_cand_idx[B_ * MAXC];
__device__ int   g_cand_cnt[B_];
__device__ float g_cand_sc[B_ * MAXC];

// ---------------------------------------------------------------- anchors
__device__ __forceinline__ void level_of(int s, int& lev, int& w, int& h, int& off) {
    if (s < 6400)      { lev = 0; w = 80; h = 80; off = 0; }
    else if (s < 8000) { lev = 1; w = 40; h = 40; off = 6400; }
    else               { lev = 2; w = 20; h = 20; off = 8000; }
}

__device__ __forceinline__ bool valid_s(int s) {
    int lev, w, h, off; level_of(s, lev, w, h, off);
    int r = s - off;
    int gy = r / w, gx = r - gy * w;
    float cx = __fdiv_rn((float)gx + 0.5f, (float)w);
    float cy = __fdiv_rn((float)gy + 0.5f, (float)h);
    float wh = 0.05f * (float)(1 << lev);
    return (cx > 0.01f) && (cx < 0.99f) && (cy > 0.01f) && (cy < 0.99f)
        && (wh > 0.01f) && (wh < 0.99f);
}

__device__ __forceinline__ void anchor4(int s, float* a) {
    int lev, w, h, off; level_of(s, lev, w, h, off);
    int r = s - off;
    int gy = r / w, gx = r - gy * w;
    float v[4];
    v[0] = __fdiv_rn((float)gx + 0.5f, (float)w);
    v[1] = __fdiv_rn((float)gy + 0.5f, (float)h);
    v[2] = 0.05f * (float)(1 << lev);
    v[3] = v[2];
#pragma unroll
    for (int c = 0; c < 4; c++) {
        float ac = fminf(fmaxf(v[c], 1e-4f), 1.0f - 1e-4f);
        a[c] = logf(__fdiv_rn(ac, 1.0f - ac));
    }
}

// ---------------------------------------------------------------- kernel A
__global__ void __launch_bounds__(256, 2) kA(
    const float* __restrict__ mem, const float* __restrict__ pw,
    const float* __restrict__ pb, const float* __restrict__ lng,
    const float* __restrict__ lnb, float* __restrict__ out_masked)
{
    __shared__ __align__(16) float Asm[64][16];
    __shared__ __align__(16) float Bsm[16][SB];
    const int t = threadIdx.x, tx = t & 15, ty = t >> 4;
    const long rowBase = (long)blockIdx.x * 64;
    const int lrow = t >> 2, kq = t & 3;
    const long aRow = rowBase + lrow;
    const int s = (int)(aRow % S_);
    const float vm = valid_s(s) ? 1.0f : 0.0f;
    const float* ap = mem + aRow * H_ + kq * 4;
    float* mp = out_masked + aRow * H_ + kq * 4;
    const float* wp = pw + (long)t * H_;

    float acc[4][16];
#pragma unroll
    for (int i = 0; i < 4; i++)
#pragma unroll
        for (int j = 0; j < 16; j++) acc[i][j] = 0.0f;

#pragma unroll 1
    for (int kb = 0; kb < H_; kb += 16) {
        float4 av = *(const float4*)(ap + kb);
        av.x *= vm; av.y *= vm; av.z *= vm; av.w *= vm;
        *(float4*)(mp + kb) = av;
        *(float4*)&Asm[lrow][kq * 4] = av;
        float4 w0 = *(const float4*)(wp + kb);
        float4 w1 = *(const float4*)(wp + kb + 4);
        float4 w2 = *(const float4*)(wp + kb + 8);
        float4 w3 = *(const float4*)(wp + kb + 12);
        Bsm[0][t] = w0.x;  Bsm[1][t] = w0.y;  Bsm[2][t] = w0.z;  Bsm[3][t] = w0.w;
        Bsm[4][t] = w1.x;  Bsm[5][t] = w1.y;  Bsm[6][t] = w1.z;  Bsm[7][t] = w1.w;
        Bsm[8][t] = w2.x;  Bsm[9][t] = w2.y;  Bsm[10][t] = w2.z; Bsm[11][t] = w2.w;
        Bsm[12][t] = w3.x; Bsm[13][t] = w3.y; Bsm[14][t] = w3.z; Bsm[15][t] = w3.w;
        __syncthreads();
#pragma unroll
        for (int kk = 0; kk < 16; kk++) {
            float a0 = Asm[ty * 4 + 0][kk];
            float a1 = Asm[ty * 4 + 1][kk];
            float a2 = Asm[ty * 4 + 2][kk];
            float a3 = Asm[ty * 4 + 3][kk];
            float bv[16];
            *(float4*)&bv[0]  = *(const float4*)&Bsm[kk][tx * 4];
            *(float4*)&bv[4]  = *(const float4*)&Bsm[kk][tx * 4 + 64];
            *(float4*)&bv[8]  = *(const float4*)&Bsm[kk][tx * 4 + 128];
            *(float4*)&bv[12] = *(const float4*)&Bsm[kk][tx * 4 + 192];
#pragma unroll
            for (int j = 0; j < 16; j++) {
                acc[0][j] += a0 * bv[j];
                acc[1][j] += a1 * bv[j];
                acc[2][j] += a2 * bv[j];
                acc[3][j] += a3 * bv[j];
            }
        }
        __syncthreads();
    }

#pragma unroll
    for (int j = 0; j < 16; j++) {
        int c = tx * 4 + (j >> 2) * 64 + (j & 3);
        float pv = pb[c];
#pragma unroll
        for (int i = 0; i < 4; i++) acc[i][j] += pv;
    }
#pragma unroll
    for (int i = 0; i < 4; i++) {
        float sum = 0.0f;
#pragma unroll
        for (int j = 0; j < 16; j++) sum += acc[i][j];
#pragma unroll
        for (int m = 8; m >= 1; m >>= 1) sum += __shfl_xor_sync(0xffffffffu, sum, m);
        float mu = sum * (1.0f / 256.0f);
        float vs = 0.0f;
#pragma unroll
        for (int j = 0; j < 16; j++) { float d = acc[i][j] - mu; vs += d * d; }
#pragma unroll
        for (int m = 8; m >= 1; m >>= 1) vs += __shfl_xor_sync(0xffffffffu, vs, m);
        float rs = rsqrtf(vs * (1.0f / 256.0f) + 1e-5f);
        long orow = rowBase + ty * 4 + i;
        float* ep = g_encoded + orow * H_;
#pragma unroll
        for (int jg = 0; jg < 4; jg++) {
            int c0 = tx * 4 + jg * 64;
            float4 o;
            o.x = (acc[i][jg * 4 + 0] - mu) * rs * lng[c0 + 0] + lnb[c0 + 0];
            o.y = (acc[i][jg * 4 + 1] - mu) * rs * lng[c0 + 1] + lnb[c0 + 1];
            o.z = (acc[i][jg * 4 + 2] - mu) * rs * lng[c0 + 2] + lnb[c0 + 2];
            o.w = (acc[i][jg * 4 + 3] - mu) * rs * lng[c0 + 3] + lnb[c0 + 3];
            *(float4*)(ep + c0) = o;
        }
    }
}

// ---------------------------------------------------------------- kernel B
__global__ void __launch_bounds__(256, 2) kB(
    const float* __restrict__ sw, const float* __restrict__ sb)
{
    __shared__ __align__(16) float Asm[64][16];
    __shared__ float Bsm[16][84];
    const int t = threadIdx.x, tx = t & 15, ty = t >> 4;
    const long rowBase = (long)blockIdx.x * 64;
    const int lrow = t >> 2, kq = t & 3;
    const float* ap = g_encoded + (rowBase + lrow) * H_ + kq * 4;

    float acc[4][5];
#pragma unroll
    for (int i = 0; i < 4; i++)
#pragma unroll
        for (int j = 0; j < 5; j++) acc[i][j] = 0.0f;

#pragma unroll 1
    for (int kb = 0; kb < H_; kb += 16) {
        float4 av = *(const float4*)(ap + kb);
        *(float4*)&Asm[lrow][kq * 4] = av;
        if (t < 80) {
            const float* wp = sw + (long)t * H_ + kb;
            float4 w0 = *(const float4*)(wp);
            float4 w1 = *(const float4*)(wp + 4);
            float4 w2 = *(const float4*)(wp + 8);
            float4 w3 = *(const float4*)(wp + 12);
            Bsm[0][t] = w0.x;  Bsm[1][t] = w0.y;  Bsm[2][t] = w0.z;  Bsm[3][t] = w0.w;
            Bsm[4][t] = w1.x;  Bsm[5][t] = w1.y;  Bsm[6][t] = w1.z;  Bsm[7][t] = w1.w;
            Bsm[8][t] = w2.x;  Bsm[9][t] = w2.y;  Bsm[10][t] = w2.z; Bsm[11][t] = w2.w;
            Bsm[12][t] = w3.x; Bsm[13][t] = w3.y; Bsm[14][t] = w3.z; Bsm[15][t] = w3.w;
        }
        __syncthreads();
#pragma unroll
        for (int kk = 0; kk < 16; kk++) {
            float a0 = Asm[ty * 4 + 0][kk];
            float a1 = Asm[ty * 4 + 1][kk];
            float a2 = Asm[ty * 4 + 2][kk];
            float a3 = Asm[ty * 4 + 3][kk];
#pragma unroll
            for (int j = 0; j < 5; j++) {
                float b = Bsm[kk][tx + 16 * j];
                acc[0][j] += a0 * b;
                acc[1][j] += a1 * b;
                acc[2][j] += a2 * b;
                acc[3][j] += a3 * b;
            }
        }
        __syncthreads();
    }
    float sbl[5];
#pragma unroll
    for (int j = 0; j < 5; j++) sbl[j] = sb[tx + 16 * j];
#pragma unroll
    for (int i = 0; i < 4; i++) {
        float mx = acc[i][0] + sbl[0];
#pragma unroll
        for (int j = 1; j < 5; j++) mx = fmaxf(mx, acc[i][j] + sbl[j]);
#pragma unroll
        for (int m = 8; m >= 1; m >>= 1) mx = fmaxf(mx, __shfl_xor_sync(0xffffffffu, mx, m));
        if (tx == 0) g_rowmax[rowBase + ty * 4 + i] = mx;
    }
}

// ---------------------------------------------------------------- kernel C
// fp32 top-300 per batch; only the rank-300 value (threshold) is kept.
__device__ __forceinline__ unsigned fordu(float f) {
    unsigned u = __float_as_uint(f);
    return (u & 0x80000000u) ? ~u : (u | 0x80000000u);
}

__global__ void __launch_bounds__(1024) kC()
{
    __shared__ float vals[S_];
    __shared__ unsigned long long wred[32];
    const int b = blockIdx.x, t = threadIdx.x;
    for (int i = t; i < S_; i += 1024) vals[i] = g_rowmax[b * S_ + i];
    __syncthreads();
    for (int k = 0; k < K_; k++) {
        unsigned long long best = 0ull;
        for (int i = t; i < S_; i += 1024) {
            unsigned long long key =
                ((unsigned long long)fordu(vals[i]) << 32) | (0xFFFFFFFFu - (unsigned)i);
            if (key > best) best = key;
        }
#pragma unroll
        for (int m = 16; m >= 1; m >>= 1) {
            unsigned long long o = __shfl_xor_sync(0xffffffffu, best, m);
            if (o > best) best = o;
        }
        if ((t & 31) == 0) wred[t >> 5] = best;
        __syncthreads();
        if (t == 0) {
            best = wred[0];
#pragma unroll
            for (int w = 1; w < 32; w++) if (wred[w] > best) best = wred[w];
            int idx = (int)(0xFFFFFFFFu - (unsigned)(best & 0xFFFFFFFFull));
            if (k == K_ - 1) g_thr[b] = vals[idx];
            vals[idx] = -INFINITY;
        }
        __syncthreads();
    }
}

// ---------------------------------------------------------------- kCand
__global__ void __launch_bounds__(1024) kCand()
{
    __shared__ int cnt;
    const int b = blockIdx.x, t = threadIdx.x;
    if (t == 0) cnt = 0;
    __syncthreads();
    float thr = g_thr[b] - 3e-3f;
    for (int i = t; i < S_; i += 1024) {
        if (g_rowmax[b * S_ + i] >= thr) {
            int p = atomicAdd(&cnt, 1);
            if (p < MAXC) g_cand_idx[b * MAXC + p] = i;
        }
    }
    __syncthreads();
    if (t == 0) g_cand_cnt[b] = cnt < MAXC ? cnt : MAXC;
}

// ---------------------------------------------------------------- kX
// Bit-exact fp32 replica of the reference (XLA:GPU / cuBLAS) score chain:
//  - GEMM: per-output sequential ascending-k FFMA chain, bias via FADD
//  - LN reductions: warp shfl_down tree + zero-padded 8-partial combine
//  - mean/var divide by 256 exact; d*d as FMUL; affine as FMUL,FMUL,FADD
//  - rsqrtf (MUFU.RSQ), same as XLA's rsqrt.approx.f32
__device__ __forceinline__ float warp_sum_down(float v) {
#pragma unroll
    for (int off = 16; off >= 1; off >>= 1)
        v = __fadd_rn(v, __shfl_down_sync(0xffffffffu, v, off));
    return v;
}

__device__ __forceinline__ float combine8(const float* p) {
    // shfl_down tree over 8 valid lanes padded with +0
    float q04 = __fadd_rn(p[0], p[4]);
    float q26 = __fadd_rn(p[2], p[6]);
    float q15 = __fadd_rn(p[1], p[5]);
    float q37 = __fadd_rn(p[3], p[7]);
    return __fadd_rn(__fadd_rn(q04, q26), __fadd_rn(q15, q37));
}

__global__ void __launch_bounds__(256) kX(
    const float* __restrict__ masked, const float* __restrict__ pw,
    const float* __restrict__ pb, const float* __restrict__ lng,
    const float* __restrict__ lnb, const float* __restrict__ sw,
    const float* __restrict__ sb)
{
    const int b = blockIdx.y, cid = blockIdx.x;
    if (cid >= g_cand_cnt[b]) return;
    const int r = g_cand_idx[b * MAXC + cid];
    const int t = threadIdx.x;
    const int lane = t & 31, warp = t >> 5;
    __shared__ float m[H_];
    __shared__ float enc[H_];
    __shared__ float part[8];
    __shared__ float mu_s, rs_s;

    m[t] = masked[((long)b * S_ + r) * H_ + t];
    __syncthreads();

    // proj column t: sequential ascending-k FFMA (cuBLAS SGEMM order)
    float acc = 0.0f;
    const float* w = pw + (long)t * H_;
#pragma unroll 8
    for (int k = 0; k < H_; k++) acc = __fmaf_rn(m[k], w[k], acc);
    float x = __fadd_rn(acc, pb[t]);

    // mean (XLA row-reduce order)
    float v = warp_sum_down(x);
    if (lane == 0) part[warp] = v;
    __syncthreads();
    if (t == 0) mu_s = __fmul_rn(combine8(part), 1.0f / 256.0f);  // /256 exact
    __syncthreads();
    float mu = mu_s;

    // variance
    float d = __fsub_rn(x, mu);
    float dd = __fmul_rn(d, d);
    v = warp_sum_down(dd);
    if (lane == 0) part[warp] = v;
    __syncthreads();
    if (t == 0) {
        float var = __fmul_rn(combine8(part), 1.0f / 256.0f);
        rs_s = rsqrtf(__fadd_rn(var, 1e-5f));
    }
    __syncthreads();
    float rs = rs_s;

    // affine: ((x-mu)*rs)*g + b
    enc[t] = __fadd_rn(__fmul_rn(__fmul_rn(d, rs), lng[t]), lnb[t]);
    __syncthreads();

    // score GEMM column t (t<80): sequential ascending-k FFMA + bias
    float sc = -INFINITY;
    if (t < C_) {
        float a2 = 0.0f;
        const float* swr = sw + (long)t * H_;
#pragma unroll 8
        for (int k = 0; k < H_; k++) a2 = __fmaf_rn(enc[k], swr[k], a2);
        sc = __fadd_rn(a2, sb[t]);
    }
    // max over classes (exact in any order)
#pragma unroll
    for (int off = 16; off >= 1; off >>= 1)
        sc = fmaxf(sc, __shfl_down_sync(0xffffffffu, sc, off));
    if (lane == 0) part[warp] = sc;
    __syncthreads();
    if (t == 0) {
        float mx = part[0];
#pragma unroll
        for (int i2 = 1; i2 < 8; i2++) mx = fmaxf(mx, part[i2]);
        g_cand_sc[b * MAXC + cid] = mx;
    }
}

// ---------------------------------------------------------------- kSel
// top-300 among candidates by replica fp32 score (desc, ties -> lowest index)
__global__ void __launch_bounds__(256) kSel()
{
    __shared__ unsigned long long keys[MAXC];
    __shared__ unsigned long long wred[8];
    const int b = blockIdx.x, t = threadIdx.x;
    const int cnt = g_cand_cnt[b];
    for (int i = t; i < MAXC; i += 256) {
        if (i < cnt) {
            unsigned idx = (unsigned)g_cand_idx[b * MAXC + i];
            keys[i] = ((unsigned long long)fordu(g_cand_sc[b * MAXC + i]) << 32)
                    | (0xFFFFFFFFu - idx);
        } else keys[i] = 0ull;
    }
    __syncthreads();
    for (int k = 0; k < K_; k++) {
        unsigned long long best = keys[t];
        if (keys[t + 256] > best) best = keys[t + 256];
#pragma unroll
        for (int m = 16; m >= 1; m >>= 1) {
            unsigned long long o = __shfl_xor_sync(0xffffffffu, best, m);
            if (o > best) best = o;
        }
        if ((t & 31) == 0) wred[t >> 5] = best;
        __syncthreads();
        unsigned long long chosen;
        if (t == 0) {
            best = wred[0];
#pragma unroll
            for (int w = 1; w < 8; w++) if (wred[w] > best) best = wred[w];
            g_topk[b * K_ + k] = (int)(0xFFFFFFFFu - (unsigned)(best & 0xFFFFFFFFull));
            wred[0] = best;
        }
        __syncthreads();
        chosen = wred[0];
        if (keys[t] == chosen) keys[t] = 0ull;
        if (keys[t + 256] == chosen) keys[t + 256] = 0ull;
        __syncthreads();
    }
}

// ---------------------------------------------------------------- kernel D
__global__ void __launch_bounds__(256, 1) kD(
    const float* __restrict__ w1, const float* __restrict__ b1,
    const float* __restrict__ w2, const float* __restrict__ b2,
    const float* __restrict__ w3, const float* __restrict__ b3,
    const float* __restrict__ sw, const float* __restrict__ sb,
    float* __restrict__ target, float* __restrict__ refp,
    float* __restrict__ boxes, float* __restrict__ logits)
{
    extern __shared__ __align__(16) float smx[];
    float* Esm = smx;
    float* Hsm = smx + 64 * SB;
    float* H2  = smx + 2 * 64 * SB;
    float* Bs  = smx + 3 * 64 * SB;
    float* w3s = Bs + 16 * SB;
    int* idxs = (int*)(w3s + 4 * SB);
    int* srcs = idxs + 64;

    const int t = threadIdx.x, tx = t & 15, ty = t >> 4;
    const long gBase = (long)blockIdx.x * 64;

    if (t < 64) {
        long g = gBase + t;
        int b = (int)(g / K_);
        int kq = (int)(g % K_);
        int idx = g_topk[b * K_ + kq];
        idxs[t] = idx;
        srcs[t] = b * S_ + idx;
    }
    __syncthreads();

    for (int f = t; f < 64 * 64; f += 256) {
        int row = f >> 6, c4 = f & 63;
        float4 v = *(const float4*)(g_encoded + (long)srcs[row] * H_ + c4 * 4);
        *(float4*)&Esm[row * SB + c4 * 4] = v;
        *(float4*)(target + (gBase + row) * H_ + c4 * 4) = v;
    }
    __syncthreads();

    float acc[4][16];

    // ---- GEMM1
#pragma unroll
    for (int i = 0; i < 4; i++)
#pragma unroll
        for (int j = 0; j < 16; j++) acc[i][j] = 0.0f;
#pragma unroll 1
    for (int kb = 0; kb < H_; kb += 16) {
        const float* wp = w1 + (long)t * H_ + kb;
        float4 q0 = *(const float4*)(wp);
        float4 q1 = *(const float4*)(wp + 4);
        float4 q2 = *(const float4*)(wp + 8);
        float4 q3 = *(const float4*)(wp + 12);
        Bs[0 * SB + t] = q0.x;  Bs[1 * SB + t] = q0.y;  Bs[2 * SB + t] = q0.z;  Bs[3 * SB + t] = q0.w;
        Bs[4 * SB + t] = q1.x;  Bs[5 * SB + t] = q1.y;  Bs[6 * SB + t] = q1.z;  Bs[7 * SB + t] = q1.w;
        Bs[8 * SB + t] = q2.x;  Bs[9 * SB + t] = q2.y;  Bs[10 * SB + t] = q2.z; Bs[11 * SB + t] = q2.w;
        Bs[12 * SB + t] = q3.x; Bs[13 * SB + t] = q3.y; Bs[14 * SB + t] = q3.z; Bs[15 * SB + t] = q3.w;
        __syncthreads();
#pragma unroll
        for (int kk = 0; kk < 16; kk++) {
            float a0 = Esm[(ty * 4 + 0) * SB + kb + kk];
            float a1 = Esm[(ty * 4 + 1) * SB + kb + kk];
            float a2 = Esm[(ty * 4 + 2) * SB + kb + kk];
            float a3 = Esm[(ty * 4 + 3) * SB + kb + kk];
            float bv[16];
            *(float4*)&bv[0]  = *(const float4*)&Bs[kk * SB + tx * 4];
            *(float4*)&bv[4]  = *(const float4*)&Bs[kk * SB + tx * 4 + 64];
            *(float4*)&bv[8]  = *(const float4*)&Bs[kk * SB + tx * 4 + 128];
            *(float4*)&bv[12] = *(const float4*)&Bs[kk * SB + tx * 4 + 192];
#pragma unroll
            for (int j = 0; j < 16; j++) {
                acc[0][j] += a0 * bv[j];
                acc[1][j] += a1 * bv[j];
                acc[2][j] += a2 * bv[j];
                acc[3][j] += a3 * bv[j];
            }
        }
        __syncthreads();
    }
#pragma unroll
    for (int j = 0; j < 16; j++) {
        int c = tx * 4 + (j >> 2) * 64 + (j & 3);
        float bb = b1[c];
#pragma unroll
        for (int i = 0; i < 4; i++)
            Hsm[(ty * 4 + i) * SB + c] = fmaxf(acc[i][j] + bb, 0.0f);
    }
    __syncthreads();

    // ---- GEMM2
#pragma unroll
    for (int i = 0; i < 4; i++)
#pragma unroll
        for (int j = 0; j < 16; j++) acc[i][j] = 0.0f;
#pragma unroll 1
    for (int kb = 0; kb < H_; kb += 16) {
        const float* wp = w2 + (long)t * H_ + kb;
        float4 q0 = *(const float4*)(wp);
        float4 q1 = *(const float4*)(wp + 4);
        float4 q2 = *(const float4*)(wp + 8);
        float4 q3 = *(const float4*)(wp + 12);
        Bs[0 * SB + t] = q0.x;  Bs[1 * SB + t] = q0.y;  Bs[2 * SB + t] = q0.z;  Bs[3 * SB + t] = q0.w;
        Bs[4 * SB + t] = q1.x;  Bs[5 * SB + t] = q1.y;  Bs[6 * SB + t] = q1.z;  Bs[7 * SB + t] = q1.w;
        Bs[8 * SB + t] = q2.x;  Bs[9 * SB + t] = q2.y;  Bs[10 * SB + t] = q2.z; Bs[11 * SB + t] = q2.w;
        Bs[12 * SB + t] = q3.x; Bs[13 * SB + t] = q3.y; Bs[14 * SB + t] = q3.z; Bs[15 * SB + t] = q3.w;
        __syncthreads();
#pragma unroll
        for (int kk = 0; kk < 16; kk++) {
            float a0 = Hsm[(ty * 4 + 0) * SB + kb + kk];
            float a1 = Hsm[(ty * 4 + 1) * SB + kb + kk];
            float a2 = Hsm[(ty * 4 + 2) * SB + kb + kk];
            float a3 = Hsm[(ty * 4 + 3) * SB + kb + kk];
            float bv[16];
            *(float4*)&bv[0]  = *(const float4*)&Bs[kk * SB + tx * 4];
            *(float4*)&bv[4]  = *(const float4*)&Bs[kk * SB + tx * 4 + 64];
            *(float4*)&bv[8]  = *(const float4*)&Bs[kk * SB + tx * 4 + 128];
            *(float4*)&bv[12] = *(const float4*)&Bs[kk * SB + tx * 4 + 192];
#pragma unroll
            for (int j = 0; j < 16; j++) {
                acc[0][j] += a0 * bv[j];
                acc[1][j] += a1 * bv[j];
                acc[2][j] += a2 * bv[j];
                acc[3][j] += a3 * bv[j];
            }
        }
        __syncthreads();
    }
#pragma unroll
    for (int j = 0; j < 16; j++) {
        int c = tx * 4 + (j >> 2) * 64 + (j & 3);
        float bb = b2[c];
#pragma unroll
        for (int i = 0; i < 4; i++)
            H2[(ty * 4 + i) * SB + c] = fmaxf(acc[i][j] + bb, 0.0f);
    }
    __syncthreads();

    // ---- logits
    float sa[4][5];
#pragma unroll
    for (int i = 0; i < 4; i++)
#pragma unroll
        for (int j = 0; j < 5; j++) sa[i][j] = 0.0f;
#pragma unroll 1
    for (int kb = 0; kb < H_; kb += 16) {
        if (t < 80) {
            const float* wp = sw + (long)t * H_ + kb;
            float4 q0 = *(const float4*)(wp);
            float4 q1 = *(const float4*)(wp + 4);
            float4 q2 = *(const float4*)(wp + 8);
            float4 q3 = *(const float4*)(wp + 12);
            Bs[0 * SB + t] = q0.x;  Bs[1 * SB + t] = q0.y;  Bs[2 * SB + t] = q0.z;  Bs[3 * SB + t] = q0.w;
            Bs[4 * SB + t] = q1.x;  Bs[5 * SB + t] = q1.y;  Bs[6 * SB + t] = q1.z;  Bs[7 * SB + t] = q1.w;
            Bs[8 * SB + t] = q2.x;  Bs[9 * SB + t] = q2.y;  Bs[10 * SB + t] = q2.z; Bs[11 * SB + t] = q2.w;
            Bs[12 * SB + t] = q3.x; Bs[13 * SB + t] = q3.y; Bs[14 * SB + t] = q3.z; Bs[15 * SB + t] = q3.w;
        }
        __syncthreads();
#pragma unroll
        for (int kk = 0; kk < 16; kk++) {
            float a0 = Esm[(ty * 4 + 0) * SB + kb + kk];
            float a1 = Esm[(ty * 4 + 1) * SB + kb + kk];
            float a2 = Esm[(ty * 4 + 2) * SB + kb + kk];
            float a3 = Esm[(ty * 4 + 3) * SB + kb + kk];
#pragma unroll
            for (int j = 0; j < 5; j++) {
                float b = Bs[kk * SB + tx + 16 * j];
                sa[0][j] += a0 * b;
                sa[1][j] += a1 * b;
                sa[2][j] += a2 * b;
                sa[3][j] += a3 * b;
            }
        }
        __syncthreads();
    }
#pragma unroll
    for (int j = 0; j < 5; j++) {
        int c = tx + 16 * j;
        float bb = sb[c];
#pragma unroll
        for (int i = 0; i < 4; i++)
            logits[(gBase + ty * 4 + i) * C_ + c] = sa[i][j] + bb;
    }

    // ---- box head
    for (int f = t; f < 4 * H_; f += 256) {
        int c = f >> 8, k = f & 255;
        w3s[c * SB + k] = w3[f];
    }
    __syncthreads();
    {
        int row = t >> 2, c = t & 3;
        float a = b3[c];
        const float* hp = H2 + row * SB;
        const float* wp3 = w3s + c * SB;
#pragma unroll 8
        for (int k = 0; k < H_; k++) a += hp[k] * wp3[k];
        float an[4];
        anchor4(idxs[row], an);
        float bu = a + an[c];
        refp[(gBase + row) * 4 + c] = bu;
        boxes[(gBase + row) * 4 + c] = __fdiv_rn(1.0f, 1.0f + expf(-bu));
    }
}

// ---------------------------------------------------------------- launch
extern "C" void kernel_launch(void* const* d_in, const int* in_sizes, int n_in,
                              void* d_out, int out_size)
{
    const float* mem = (const float*)d_in[0];
    const float* pw  = (const float*)d_in[2];
    const float* pb  = (const float*)d_in[3];
    const float* lng = (const float*)d_in[4];
    const float* lnb = (const float*)d_in[5];
    const float* sw  = (const float*)d_in[6];
    const float* sb  = (const float*)d_in[7];
    const float* w1  = (const float*)d_in[8];
    const float* b1  = (const float*)d_in[9];
    const float* w2  = (const float*)d_in[10];
    const float* b2  = (const float*)d_in[11];
    const float* w3  = (const float*)d_in[12];
    const float* b3  = (const float*)d_in[13];

    float* out = (float*)d_out;
    float* target = out + OFF_TARGET;
    float* refp   = out + OFF_REFP;
    float* boxes  = out + OFF_BOXES;
    float* logits = out + OFF_LOGITS;
    float* masked = out + OFF_MASKED;

    kA<<<ROWS_TOTAL / 64, 256>>>(mem, pw, pb, lng, lnb, masked);
    kB<<<ROWS_TOTAL / 64, 256>>>(sw, sb);
    kC<<<B_, 1024>>>();
    kCand<<<B_, 1024>>>();
    kX<<<dim3(MAXC, B_), 256>>>(masked, pw, pb, lng, lnb, sw, sb);
    kSel<<<B_, 256>>>();

    const int kd_smem = (3 * 64 * SB + 16 * SB + 4 * SB) * 4 + 128 * 4;
    cudaFuncSetAttribute(kD, cudaFuncAttributeMaxDynamicSharedMemorySize, kd_smem);
    kD<<<(B_ * K_) / 64, 256, kd_smem>>>(w1, b1, w2, b2, w3, b3, sw, sb,
                                         target, refp, boxes, logits);
}

// round 5
// speedup vs baseline: 1.0633x; 1.0633x over previous
#include <cuda_runtime.h>
#include <math.h>

#define B_ 32
#define S_ 8400
#define H_ 256
#define C_ 80
#define K_ 300
#define ROWS_TOTAL (B_*S_)
#define SB 260
#define MAXC 512

// Output layout (flattened reference tuple, row-major, fp32):
#define OFF_TARGET 0
#define OFF_REFP   2457600
#define OFF_BOXES  2496000
#define OFF_LOGITS 2534400
#define OFF_MASKED 3302400

__device__ float g_encoded[(size_t)ROWS_TOTAL * H_];   // 275 MB scratch
__device__ float g_rowmax[ROWS_TOTAL];
__device__ int   g_topk[B_ * K_];
__device__ float g_thr[B_];
__device__ int   g_cand_idx[B_ * MAXC];
__device__ int   g_cand_cnt[B_];
__device__ float g_cand_sc[B_ * MAXC];

// ---------------------------------------------------------------- anchors
__device__ __forceinline__ void level_of(int s, int& lev, int& w, int& h, int& off) {
    if (s < 6400)      { lev = 0; w = 80; h = 80; off = 0; }
    else if (s < 8000) { lev = 1; w = 40; h = 40; off = 6400; }
    else               { lev = 2; w = 20; h = 20; off = 8000; }
}

__device__ __forceinline__ bool valid_s(int s) {
    int lev, w, h, off; level_of(s, lev, w, h, off);
    int r = s - off;
    int gy = r / w, gx = r - gy * w;
    float cx = __fdiv_rn((float)gx + 0.5f, (float)w);
    float cy = __fdiv_rn((float)gy + 0.5f, (float)h);
    float wh = 0.05f * (float)(1 << lev);
    return (cx > 0.01f) && (cx < 0.99f) && (cy > 0.01f) && (cy < 0.99f)
        && (wh > 0.01f) && (wh < 0.99f);
}

__device__ __forceinline__ void anchor4(int s, float* a) {
    int lev, w, h, off; level_of(s, lev, w, h, off);
    int r = s - off;
    int gy = r / w, gx = r - gy * w;
    float v[4];
    v[0] = __fdiv_rn((float)gx + 0.5f, (float)w);
    v[1] = __fdiv_rn((float)gy + 0.5f, (float)h);
    v[2] = 0.05f * (float)(1 << lev);
    v[3] = v[2];
#pragma unroll
    for (int c = 0; c < 4; c++) {
        float ac = fminf(fmaxf(v[c], 1e-4f), 1.0f - 1e-4f);
        a[c] = logf(__fdiv_rn(ac, 1.0f - ac));
    }
}

// ---------------------------------------------------------------- kernel A
// masked_memory + proj GEMM + bias + LayerNorm -> g_encoded
// 64 rows x 256 cols per block; 256 threads; 8x8 microtile; double-buffered.
__global__ void __launch_bounds__(256, 2) kA(
    const float* __restrict__ mem, const float* __restrict__ pw,
    const float* __restrict__ pb, const float* __restrict__ lng,
    const float* __restrict__ lnb, float* __restrict__ out_masked)
{
    __shared__ __align__(16) float Asm[2][8][64];
    __shared__ __align__(16) float Bsm[2][8][256];
    __shared__ float vmask[64];
    const int t = threadIdx.x;
    const int tc = t & 31, tr = t >> 5;          // warp tr owns rows tr*8..+7
    const long rowBase = (long)blockIdx.x * 64;

    if (t < 64) vmask[t] = valid_s((int)((rowBase + t) % S_)) ? 1.0f : 0.0f;
    __syncthreads();

    // A loader: t<128 -> row=t>>1, q=t&1 loads mem[row][kb+q*4..+3]
    const int arow = t >> 1, aq = t & 1;
    const float* aPtr = mem + (rowBase + (arow & 63)) * H_ + aq * 4;
    float* mPtr = out_masked + (rowBase + (arow & 63)) * H_ + aq * 4;
    const float avm = vmask[arow & 63];          // in-bounds for all t; unused when t>=128
    // B loader: two f4: c0=t>>1 (q=t&1), c1=128+(t>>1)
    const int bc = t >> 1, bq = t & 1;
    const float* bPtr0 = pw + (long)bc * H_ + bq * 4;
    const float* bPtr1 = pw + (long)(128 + bc) * H_ + bq * 4;

    float4 aR, bR0, bR1;
    // load tile 0
    if (t < 128) {
        aR = *(const float4*)(aPtr);
        aR.x *= avm; aR.y *= avm; aR.z *= avm; aR.w *= avm;
    }
    bR0 = *(const float4*)(bPtr0);
    bR1 = *(const float4*)(bPtr1);
    // store tile 0
    if (t < 128) {
        *(float4*)(mPtr) = aR;
        Asm[0][aq * 4 + 0][arow] = aR.x;
        Asm[0][aq * 4 + 1][arow] = aR.y;
        Asm[0][aq * 4 + 2][arow] = aR.z;
        Asm[0][aq * 4 + 3][arow] = aR.w;
    }
    Bsm[0][bq * 4 + 0][bc] = bR0.x;  Bsm[0][bq * 4 + 1][bc] = bR0.y;
    Bsm[0][bq * 4 + 2][bc] = bR0.z;  Bsm[0][bq * 4 + 3][bc] = bR0.w;
    Bsm[0][bq * 4 + 0][128 + bc] = bR1.x;  Bsm[0][bq * 4 + 1][128 + bc] = bR1.y;
    Bsm[0][bq * 4 + 2][128 + bc] = bR1.z;  Bsm[0][bq * 4 + 3][128 + bc] = bR1.w;
    __syncthreads();

    float acc[8][8];
#pragma unroll
    for (int i = 0; i < 8; i++)
#pragma unroll
        for (int j = 0; j < 8; j++) acc[i][j] = 0.0f;

#pragma unroll 1
    for (int ib = 0; ib < 32; ib++) {
        const int cur = ib & 1;
        const int kb = (ib + 1) * 8;
        if (ib < 31) {
            if (t < 128) {
                aR = *(const float4*)(aPtr + kb);
                aR.x *= avm; aR.y *= avm; aR.z *= avm; aR.w *= avm;
            }
            bR0 = *(const float4*)(bPtr0 + kb);
            bR1 = *(const float4*)(bPtr1 + kb);
        }
#pragma unroll
        for (int kk = 0; kk < 8; kk++) {
            float4 av0 = *(const float4*)&Asm[cur][kk][tr * 8];
            float4 av1 = *(const float4*)&Asm[cur][kk][tr * 8 + 4];
            float4 bv0 = *(const float4*)&Bsm[cur][kk][tc * 4];
            float4 bv1 = *(const float4*)&Bsm[cur][kk][128 + tc * 4];
            float a[8] = {av0.x, av0.y, av0.z, av0.w, av1.x, av1.y, av1.z, av1.w};
            float b[8] = {bv0.x, bv0.y, bv0.z, bv0.w, bv1.x, bv1.y, bv1.z, bv1.w};
#pragma unroll
            for (int i = 0; i < 8; i++)
#pragma unroll
                for (int j = 0; j < 8; j++)
                    acc[i][j] = __fmaf_rn(a[i], b[j], acc[i][j]);
        }
        if (ib < 31) {
            const int nxt = cur ^ 1;
            if (t < 128) {
                *(float4*)(mPtr + kb) = aR;
                Asm[nxt][aq * 4 + 0][arow] = aR.x;
                Asm[nxt][aq * 4 + 1][arow] = aR.y;
                Asm[nxt][aq * 4 + 2][arow] = aR.z;
                Asm[nxt][aq * 4 + 3][arow] = aR.w;
            }
            Bsm[nxt][bq * 4 + 0][bc] = bR0.x;  Bsm[nxt][bq * 4 + 1][bc] = bR0.y;
            Bsm[nxt][bq * 4 + 2][bc] = bR0.z;  Bsm[nxt][bq * 4 + 3][bc] = bR0.w;
            Bsm[nxt][bq * 4 + 0][128 + bc] = bR1.x;  Bsm[nxt][bq * 4 + 1][128 + bc] = bR1.y;
            Bsm[nxt][bq * 4 + 2][128 + bc] = bR1.z;  Bsm[nxt][bq * 4 + 3][128 + bc] = bR1.w;
            __syncthreads();
        }
    }

    // epilogue: bias + LayerNorm; row r = rowBase + tr*8 + i, cols tc*4 & 128+tc*4
    float pb0[4], pb1[4], g0[4], g1[4], be0[4], be1[4];
    *(float4*)pb0 = *(const float4*)(pb + tc * 4);
    *(float4*)pb1 = *(const float4*)(pb + 128 + tc * 4);
    *(float4*)g0  = *(const float4*)(lng + tc * 4);
    *(float4*)g1  = *(const float4*)(lng + 128 + tc * 4);
    *(float4*)be0 = *(const float4*)(lnb + tc * 4);
    *(float4*)be1 = *(const float4*)(lnb + 128 + tc * 4);

#pragma unroll
    for (int i = 0; i < 8; i++) {
#pragma unroll
        for (int j = 0; j < 4; j++) { acc[i][j] += pb0[j]; acc[i][j + 4] += pb1[j]; }
        float sum = 0.0f;
#pragma unroll
        for (int j = 0; j < 8; j++) sum += acc[i][j];
#pragma unroll
        for (int m = 16; m >= 1; m >>= 1) sum += __shfl_xor_sync(0xffffffffu, sum, m);
        float mu = sum * (1.0f / 256.0f);
        float vs = 0.0f;
#pragma unroll
        for (int j = 0; j < 8; j++) { float d = acc[i][j] - mu; vs += d * d; }
#pragma unroll
        for (int m = 16; m >= 1; m >>= 1) vs += __shfl_xor_sync(0xffffffffu, vs, m);
        float rs = rsqrtf(vs * (1.0f / 256.0f) + 1e-5f);
        float* ep = g_encoded + (rowBase + tr * 8 + i) * H_;
        float4 o0, o1;
        o0.x = (acc[i][0] - mu) * rs * g0[0] + be0[0];
        o0.y = (acc[i][1] - mu) * rs * g0[1] + be0[1];
        o0.z = (acc[i][2] - mu) * rs * g0[2] + be0[2];
        o0.w = (acc[i][3] - mu) * rs * g0[3] + be0[3];
        o1.x = (acc[i][4] - mu) * rs * g1[0] + be1[0];
        o1.y = (acc[i][5] - mu) * rs * g1[1] + be1[1];
        o1.z = (acc[i][6] - mu) * rs * g1[2] + be1[2];
        o1.w = (acc[i][7] - mu) * rs * g1[3] + be1[3];
        *(float4*)(ep + tc * 4) = o0;
        *(float4*)(ep + 128 + tc * 4) = o1;
    }
}

// ---------------------------------------------------------------- kernel B
// scores rowmax: max_c (encoded @ score_w^T + score_b)
// 128 rows x 80 cols per block; 256 threads; 8x5 microtile; double-buffered.
__global__ void __launch_bounds__(256, 2) kB(
    const float* __restrict__ sw, const float* __restrict__ sb)
{
    __shared__ __align__(16) float Asm[2][8][128];
    __shared__ __align__(16) float Bsm[2][8][80];
    const int t = threadIdx.x;
    const int tc = t & 15, tr = t >> 4;          // rows tr*8..+7, cols tc*5..+4
    const long rowBase = (long)blockIdx.x * 128;

    const int arow = t >> 1, aq = t & 1;
    const float* aPtr = g_encoded + (rowBase + arow) * H_ + aq * 4;
    const int bc = t >> 1, bq = t & 1;            // valid if t<160
    const float* bPtr = sw + (long)(bc < C_ ? bc : 0) * H_ + bq * 4;

    float4 aR, bR;
    aR = *(const float4*)(aPtr);
    if (t < 160) bR = *(const float4*)(bPtr);
    Asm[0][aq * 4 + 0][arow] = aR.x;
    Asm[0][aq * 4 + 1][arow] = aR.y;
    Asm[0][aq * 4 + 2][arow] = aR.z;
    Asm[0][aq * 4 + 3][arow] = aR.w;
    if (t < 160) {
        Bsm[0][bq * 4 + 0][bc] = bR.x;  Bsm[0][bq * 4 + 1][bc] = bR.y;
        Bsm[0][bq * 4 + 2][bc] = bR.z;  Bsm[0][bq * 4 + 3][bc] = bR.w;
    }
    __syncthreads();

    float acc[8][5];
#pragma unroll
    for (int i = 0; i < 8; i++)
#pragma unroll
        for (int j = 0; j < 5; j++) acc[i][j] = 0.0f;

#pragma unroll 1
    for (int ib = 0; ib < 32; ib++) {
        const int cur = ib & 1;
        const int kb = (ib + 1) * 8;
        if (ib < 31) {
            aR = *(const float4*)(aPtr + kb);
            if (t < 160) bR = *(const float4*)(bPtr + kb);
        }
#pragma unroll
        for (int kk = 0; kk < 8; kk++) {
            float4 av0 = *(const float4*)&Asm[cur][kk][tr * 8];
            float4 av1 = *(const float4*)&Asm[cur][kk][tr * 8 + 4];
            float a[8] = {av0.x, av0.y, av0.z, av0.w, av1.x, av1.y, av1.z, av1.w};
            float b[5];
#pragma unroll
            for (int j = 0; j < 5; j++) b[j] = Bsm[cur][kk][tc * 5 + j];
#pragma unroll
            for (int i = 0; i < 8; i++)
#pragma unroll
                for (int j = 0; j < 5; j++)
                    acc[i][j] = __fmaf_rn(a[i], b[j], acc[i][j]);
        }
        if (ib < 31) {
            const int nxt = cur ^ 1;
            Asm[nxt][aq * 4 + 0][arow] = aR.x;
            Asm[nxt][aq * 4 + 1][arow] = aR.y;
            Asm[nxt][aq * 4 + 2][arow] = aR.z;
            Asm[nxt][aq * 4 + 3][arow] = aR.w;
            if (t < 160) {
                Bsm[nxt][bq * 4 + 0][bc] = bR.x;  Bsm[nxt][bq * 4 + 1][bc] = bR.y;
                Bsm[nxt][bq * 4 + 2][bc] = bR.z;  Bsm[nxt][bq * 4 + 3][bc] = bR.w;
            }
            __syncthreads();
        }
    }

    float sbl[5];
#pragma unroll
    for (int j = 0; j < 5; j++) sbl[j] = sb[tc * 5 + j];
#pragma unroll
    for (int i = 0; i < 8; i++) {
        float mx = acc[i][0] + sbl[0];
#pragma unroll
        for (int j = 1; j < 5; j++) mx = fmaxf(mx, acc[i][j] + sbl[j]);
#pragma unroll
        for (int m = 8; m >= 1; m >>= 1) mx = fmaxf(mx, __shfl_xor_sync(0xffffffffu, mx, m));
        if (tc == 0) g_rowmax[rowBase + tr * 8 + i] = mx;
    }
}

// ---------------------------------------------------------------- kernel C
// fp32 top-300 per batch; only the rank-300 value (threshold) is kept.
__device__ __forceinline__ unsigned fordu(float f) {
    unsigned u = __float_as_uint(f);
    return (u & 0x80000000u) ? ~u : (u | 0x80000000u);
}

__global__ void __launch_bounds__(1024) kC()
{
    __shared__ float vals[S_];
    __shared__ unsigned long long wred[32];
    const int b = blockIdx.x, t = threadIdx.x;
    for (int i = t; i < S_; i += 1024) vals[i] = g_rowmax[b * S_ + i];
    __syncthreads();
    for (int k = 0; k < K_; k++) {
        unsigned long long best = 0ull;
        for (int i = t; i < S_; i += 1024) {
            unsigned long long key =
                ((unsigned long long)fordu(vals[i]) << 32) | (0xFFFFFFFFu - (unsigned)i);
            if (key > best) best = key;
        }
#pragma unroll
        for (int m = 16; m >= 1; m >>= 1) {
            unsigned long long o = __shfl_xor_sync(0xffffffffu, best, m);
            if (o > best) best = o;
        }
        if ((t & 31) == 0) wred[t >> 5] = best;
        __syncthreads();
        if (t == 0) {
            best = wred[0];
#pragma unroll
            for (int w = 1; w < 32; w++) if (wred[w] > best) best = wred[w];
            int idx = (int)(0xFFFFFFFFu - (unsigned)(best & 0xFFFFFFFFull));
            if (k == K_ - 1) g_thr[b] = vals[idx];
            vals[idx] = -INFINITY;
        }
        __syncthreads();
    }
}

// ---------------------------------------------------------------- kCand
__global__ void __launch_bounds__(1024) kCand()
{
    __shared__ int cnt;
    const int b = blockIdx.x, t = threadIdx.x;
    if (t == 0) cnt = 0;
    __syncthreads();
    float thr = g_thr[b] - 3e-3f;
    for (int i = t; i < S_; i += 1024) {
        if (g_rowmax[b * S_ + i] >= thr) {
            int p = atomicAdd(&cnt, 1);
            if (p < MAXC) g_cand_idx[b * MAXC + p] = i;
        }
    }
    __syncthreads();
    if (t == 0) g_cand_cnt[b] = cnt < MAXC ? cnt : MAXC;
}

// ---------------------------------------------------------------- kX
// Bit-exact fp32 replica of the reference (XLA:GPU / cuBLAS) score chain.
__device__ __forceinline__ float warp_sum_down(float v) {
#pragma unroll
    for (int off = 16; off >= 1; off >>= 1)
        v = __fadd_rn(v, __shfl_down_sync(0xffffffffu, v, off));
    return v;
}

__device__ __forceinline__ float combine8(const float* p) {
    float q04 = __fadd_rn(p[0], p[4]);
    float q26 = __fadd_rn(p[2], p[6]);
    float q15 = __fadd_rn(p[1], p[5]);
    float q37 = __fadd_rn(p[3], p[7]);
    return __fadd_rn(__fadd_rn(q04, q26), __fadd_rn(q15, q37));
}

__global__ void __launch_bounds__(256) kX(
    const float* __restrict__ masked, const float* __restrict__ pw,
    const float* __restrict__ pb, const float* __restrict__ lng,
    const float* __restrict__ lnb, const float* __restrict__ sw,
    const float* __restrict__ sb)
{
    const int b = blockIdx.y, cid = blockIdx.x;
    if (cid >= g_cand_cnt[b]) return;
    const int r = g_cand_idx[b * MAXC + cid];
    const int t = threadIdx.x;
    const int lane = t & 31, warp = t >> 5;
    __shared__ float m[H_];
    __shared__ float enc[H_];
    __shared__ float part[8];
    __shared__ float mu_s, rs_s;

    m[t] = masked[((long)b * S_ + r) * H_ + t];
    __syncthreads();

    float acc = 0.0f;
    const float* w = pw + (long)t * H_;
#pragma unroll 8
    for (int k = 0; k < H_; k++) acc = __fmaf_rn(m[k], w[k], acc);
    float x = __fadd_rn(acc, pb[t]);

    float v = warp_sum_down(x);
    if (lane == 0) part[warp] = v;
    __syncthreads();
    if (t == 0) mu_s = __fmul_rn(combine8(part), 1.0f / 256.0f);
    __syncthreads();
    float mu = mu_s;

    float d = __fsub_rn(x, mu);
    float dd = __fmul_rn(d, d);
    v = warp_sum_down(dd);
    if (lane == 0) part[warp] = v;
    __syncthreads();
    if (t == 0) {
        float var = __fmul_rn(combine8(part), 1.0f / 256.0f);
        rs_s = rsqrtf(__fadd_rn(var, 1e-5f));
    }
    __syncthreads();
    float rs = rs_s;

    enc[t] = __fadd_rn(__fmul_rn(__fmul_rn(d, rs), lng[t]), lnb[t]);
    __syncthreads();

    float sc = -INFINITY;
    if (t < C_) {
        float a2 = 0.0f;
        const float* swr = sw + (long)t * H_;
#pragma unroll 8
        for (int k = 0; k < H_; k++) a2 = __fmaf_rn(enc[k], swr[k], a2);
        sc = __fadd_rn(a2, sb[t]);
    }
#pragma unroll
    for (int off = 16; off >= 1; off >>= 1)
        sc = fmaxf(sc, __shfl_down_sync(0xffffffffu, sc, off));
    if (lane == 0) part[warp] = sc;
    __syncthreads();
    if (t == 0) {
        float mx = part[0];
#pragma unroll
        for (int i2 = 1; i2 < 8; i2++) mx = fmaxf(mx, part[i2]);
        g_cand_sc[b * MAXC + cid] = mx;
    }
}

// ---------------------------------------------------------------- kSel
__global__ void __launch_bounds__(256) kSel()
{
    __shared__ unsigned long long keys[MAXC];
    __shared__ unsigned long long wred[8];
    const int b = blockIdx.x, t = threadIdx.x;
    const int cnt = g_cand_cnt[b];
    for (int i = t; i < MAXC; i += 256) {
        if (i < cnt) {
            unsigned idx = (unsigned)g_cand_idx[b * MAXC + i];
            keys[i] = ((unsigned long long)fordu(g_cand_sc[b * MAXC + i]) << 32)
                    | (0xFFFFFFFFu - idx);
        } else keys[i] = 0ull;
    }
    __syncthreads();
    for (int k = 0; k < K_; k++) {
        unsigned long long best = keys[t];
        if (keys[t + 256] > best) best = keys[t + 256];
#pragma unroll
        for (int m = 16; m >= 1; m >>= 1) {
            unsigned long long o = __shfl_xor_sync(0xffffffffu, best, m);
            if (o > best) best = o;
        }
        if ((t & 31) == 0) wred[t >> 5] = best;
        __syncthreads();
        unsigned long long chosen;
        if (t == 0) {
            best = wred[0];
#pragma unroll
            for (int w = 1; w < 8; w++) if (wred[w] > best) best = wred[w];
            g_topk[b * K_ + k] = (int)(0xFFFFFFFFu - (unsigned)(best & 0xFFFFFFFFull));
            wred[0] = best;
        }
        __syncthreads();
        chosen = wred[0];
        if (keys[t] == chosen) keys[t] = 0ull;
        if (keys[t + 256] == chosen) keys[t + 256] = 0ull;
        __syncthreads();
    }
}

// ---------------------------------------------------------------- kernel D
__global__ void __launch_bounds__(256, 1) kD(
    const float* __restrict__ w1, const float* __restrict__ b1,
    const float* __restrict__ w2, const float* __restrict__ b2,
    const float* __restrict__ w3, const float* __restrict__ b3,
    const float* __restrict__ sw, const float* __restrict__ sb,
    float* __restrict__ target, float* __restrict__ refp,
    float* __restrict__ boxes, float* __restrict__ logits)
{
    extern __shared__ __align__(16) float smx[];
    float* Esm = smx;
    float* Hsm = smx + 64 * SB;
    float* H2  = smx + 2 * 64 * SB;
    float* Bs  = smx + 3 * 64 * SB;
    float* w3s = Bs + 16 * SB;
    int* idxs = (int*)(w3s + 4 * SB);
    int* srcs = idxs + 64;

    const int t = threadIdx.x, tx = t & 15, ty = t >> 4;
    const long gBase = (long)blockIdx.x * 64;

    if (t < 64) {
        long g = gBase + t;
        int b = (int)(g / K_);
        int kq = (int)(g % K_);
        int idx = g_topk[b * K_ + kq];
        idxs[t] = idx;
        srcs[t] = b * S_ + idx;
    }
    __syncthreads();

    for (int f = t; f < 64 * 64; f += 256) {
        int row = f >> 6, c4 = f & 63;
        float4 v = *(const float4*)(g_encoded + (long)srcs[row] * H_ + c4 * 4);
        *(float4*)&Esm[row * SB + c4 * 4] = v;
        *(float4*)(target + (gBase + row) * H_ + c4 * 4) = v;
    }
    __syncthreads();

    float acc[4][16];

    // ---- GEMM1
#pragma unroll
    for (int i = 0; i < 4; i++)
#pragma unroll
        for (int j = 0; j < 16; j++) acc[i][j] = 0.0f;
#pragma unroll 1
    for (int kb = 0; kb < H_; kb += 16) {
        const float* wp = w1 + (long)t * H_ + kb;
        float4 q0 = *(const float4*)(wp);
        float4 q1 = *(const float4*)(wp + 4);
        float4 q2 = *(const float4*)(wp + 8);
        float4 q3 = *(const float4*)(wp + 12);
        Bs[0 * SB + t] = q0.x;  Bs[1 * SB + t] = q0.y;  Bs[2 * SB + t] = q0.z;  Bs[3 * SB + t] = q0.w;
        Bs[4 * SB + t] = q1.x;  Bs[5 * SB + t] = q1.y;  Bs[6 * SB + t] = q1.z;  Bs[7 * SB + t] = q1.w;
        Bs[8 * SB + t] = q2.x;  Bs[9 * SB + t] = q2.y;  Bs[10 * SB + t] = q2.z; Bs[11 * SB + t] = q2.w;
        Bs[12 * SB + t] = q3.x; Bs[13 * SB + t] = q3.y; Bs[14 * SB + t] = q3.z; Bs[15 * SB + t] = q3.w;
        __syncthreads();
#pragma unroll
        for (int kk = 0; kk < 16; kk++) {
            float a0 = Esm[(ty * 4 + 0) * SB + kb + kk];
            float a1 = Esm[(ty * 4 + 1) * SB + kb + kk];
            float a2 = Esm[(ty * 4 + 2) * SB + kb + kk];
            float a3 = Esm[(ty * 4 + 3) * SB + kb + kk];
            float bv[16];
            *(float4*)&bv[0]  = *(const float4*)&Bs[kk * SB + tx * 4];
            *(float4*)&bv[4]  = *(const float4*)&Bs[kk * SB + tx * 4 + 64];
            *(float4*)&bv[8]  = *(const float4*)&Bs[kk * SB + tx * 4 + 128];
            *(float4*)&bv[12] = *(const float4*)&Bs[kk * SB + tx * 4 + 192];
#pragma unroll
            for (int j = 0; j < 16; j++) {
                acc[0][j] += a0 * bv[j];
                acc[1][j] += a1 * bv[j];
                acc[2][j] += a2 * bv[j];
                acc[3][j] += a3 * bv[j];
            }
        }
        __syncthreads();
    }
#pragma unroll
    for (int j = 0; j < 16; j++) {
        int c = tx * 4 + (j >> 2) * 64 + (j & 3);
        float bb = b1[c];
#pragma unroll
        for (int i = 0; i < 4; i++)
            Hsm[(ty * 4 + i) * SB + c] = fmaxf(acc[i][j] + bb, 0.0f);
    }
    __syncthreads();

    // ---- GEMM2
#pragma unroll
    for (int i = 0; i < 4; i++)
#pragma unroll
        for (int j = 0; j < 16; j++) acc[i][j] = 0.0f;
#pragma unroll 1
    for (int kb = 0; kb < H_; kb += 16) {
        const float* wp = w2 + (long)t * H_ + kb;
        float4 q0 = *(const float4*)(wp);
        float4 q1 = *(const float4*)(wp + 4);
        float4 q2 = *(const float4*)(wp + 8);
        float4 q3 = *(const float4*)(wp + 12);
        Bs[0 * SB + t] = q0.x;  Bs[1 * SB + t] = q0.y;  Bs[2 * SB + t] = q0.z;  Bs[3 * SB + t] = q0.w;
        Bs[4 * SB + t] = q1.x;  Bs[5 * SB + t] = q1.y;  Bs[6 * SB + t] = q1.z;  Bs[7 * SB + t] = q1.w;
        Bs[8 * SB + t] = q2.x;  Bs[9 * SB + t] = q2.y;  Bs[10 * SB + t] = q2.z; Bs[11 * SB + t] = q2.w;
        Bs[12 * SB + t] = q3.x; Bs[13 * SB + t] = q3.y; Bs[14 * SB + t] = q3.z; Bs[15 * SB + t] = q3.w;
        __syncthreads();
#pragma unroll
        for (int kk = 0; kk < 16; kk++) {
            float a0 = Hsm[(ty * 4 + 0) * SB + kb + kk];
            float a1 = Hsm[(ty * 4 + 1) * SB + kb + kk];
            float a2 = Hsm[(ty * 4 + 2) * SB + kb + kk];
            float a3 = Hsm[(ty * 4 + 3) * SB + kb + kk];
            float bv[16];
            *(float4*)&bv[0]  = *(const float4*)&Bs[kk * SB + tx * 4];
            *(float4*)&bv[4]  = *(const float4*)&Bs[kk * SB + tx * 4 + 64];
            *(float4*)&bv[8]  = *(const float4*)&Bs[kk * SB + tx * 4 + 128];
            *(float4*)&bv[12] = *(const float4*)&Bs[kk * SB + tx * 4 + 192];
#pragma unroll
            for (int j = 0; j < 16; j++) {
                acc[0][j] += a0 * bv[j];
                acc[1][j] += a1 * bv[j];
                acc[2][j] += a2 * bv[j];
                acc[3][j] += a3 * bv[j];
            }
        }
        __syncthreads();
    }
#pragma unroll
    for (int j = 0; j < 16; j++) {
        int c = tx * 4 + (j >> 2) * 64 + (j & 3);
        float bb = b2[c];
#pragma unroll
        for (int i = 0; i < 4; i++)
            H2[(ty * 4 + i) * SB + c] = fmaxf(acc[i][j] + bb, 0.0f);
    }
    __syncthreads();

    // ---- logits
    float sa[4][5];
#pragma unroll
    for (int i = 0; i < 4; i++)
#pragma unroll
        for (int j = 0; j < 5; j++) sa[i][j] = 0.0f;
#pragma unroll 1
    for (int kb = 0; kb < H_; kb += 16) {
        if (t < 80) {
            const float* wp = sw + (long)t * H_ + kb;
            float4 q0 = *(const float4*)(wp);
            float4 q1 = *(const float4*)(wp + 4);
            float4 q2 = *(const float4*)(wp + 8);
            float4 q3 = *(const float4*)(wp + 12);
            Bs[0 * SB + t] = q0.x;  Bs[1 * SB + t] = q0.y;  Bs[2 * SB + t] = q0.z;  Bs[3 * SB + t] = q0.w;
            Bs[4 * SB + t] = q1.x;  Bs[5 * SB + t] = q1.y;  Bs[6 * SB + t] = q1.z;  Bs[7 * SB + t] = q1.w;
            Bs[8 * SB + t] = q2.x;  Bs[9 * SB + t] = q2.y;  Bs[10 * SB + t] = q2.z; Bs[11 * SB + t] = q2.w;
            Bs[12 * SB + t] = q3.x; Bs[13 * SB + t] = q3.y; Bs[14 * SB + t] = q3.z; Bs[15 * SB + t] = q3.w;
        }
        __syncthreads();
#pragma unroll
        for (int kk = 0; kk < 16; kk++) {
            float a0 = Esm[(ty * 4 + 0) * SB + kb + kk];
            float a1 = Esm[(ty * 4 + 1) * SB + kb + kk];
            float a2 = Esm[(ty * 4 + 2) * SB + kb + kk];
            float a3 = Esm[(ty * 4 + 3) * SB + kb + kk];
#pragma unroll
            for (int j = 0; j < 5; j++) {
                float b = Bs[kk * SB + tx + 16 * j];
                sa[0][j] += a0 * b;
                sa[1][j] += a1 * b;
                sa[2][j] += a2 * b;
                sa[3][j] += a3 * b;
            }
        }
        __syncthreads();
    }
#pragma unroll
    for (int j = 0; j < 5; j++) {
        int c = tx + 16 * j;
        float bb = sb[c];
#pragma unroll
        for (int i = 0; i < 4; i++)
            logits[(gBase + ty * 4 + i) * C_ + c] = sa[i][j] + bb;
    }

    // ---- box head
    for (int f = t; f < 4 * H_; f += 256) {
        int c = f >> 8, k = f & 255;
        w3s[c * SB + k] = w3[f];
    }
    __syncthreads();
    {
        int row = t >> 2, c = t & 3;
        float a = b3[c];
        const float* hp = H2 + row * SB;
        const float* wp3 = w3s + c * SB;
#pragma unroll 8
        for (int k = 0; k < H_; k++) a += hp[k] * wp3[k];
        float an[4];
        anchor4(idxs[row], an);
        float bu = a + an[c];
        refp[(gBase + row) * 4 + c] = bu;
        boxes[(gBase + row) * 4 + c] = __fdiv_rn(1.0f, 1.0f + expf(-bu));
    }
}

// ---------------------------------------------------------------- launch
extern "C" void kernel_launch(void* const* d_in, const int* in_sizes, int n_in,
                              void* d_out, int out_size)
{
    const float* mem = (const float*)d_in[0];
    const float* pw  = (const float*)d_in[2];
    const float* pb  = (const float*)d_in[3];
    const float* lng = (const float*)d_in[4];
    const float* lnb = (const float*)d_in[5];
    const float* sw  = (const float*)d_in[6];
    const float* sb  = (const float*)d_in[7];
    const float* w1  = (const float*)d_in[8];
    const float* b1  = (const float*)d_in[9];
    const float* w2  = (const float*)d_in[10];
    const float* b2  = (const float*)d_in[11];
    const float* w3  = (const float*)d_in[12];
    const float* b3  = (const float*)d_in[13];

    float* out = (float*)d_out;
    float* target = out + OFF_TARGET;
    float* refp   = out + OFF_REFP;
    float* boxes  = out + OFF_BOXES;
    float* logits = out + OFF_LOGITS;
    float* masked = out + OFF_MASKED;

    kA<<<ROWS_TOTAL / 64, 256>>>(mem, pw, pb, lng, lnb, masked);
    kB<<<ROWS_TOTAL / 128, 256>>>(sw, sb);
    kC<<<B_, 1024>>>();
    kCand<<<B_, 1024>>>();
    kX<<<dim3(MAXC, B_), 256>>>(masked, pw, pb, lng, lnb, sw, sb);
    kSel<<<B_, 256>>>();

    const int kd_smem = (3 * 64 * SB + 16 * SB + 4 * SB) * 4 + 128 * 4;
    cudaFuncSetAttribute(kD, cudaFuncAttributeMaxDynamicSharedMemorySize, kd_smem);
    kD<<<(B_ * K_) / 64, 256, kd_smem>>>(w1, b1, w2, b2, w3, b3, sw, sb,
                                         target, refp, boxes, logits);
}